// round 1
// baseline (speedup 1.0000x reference)
#include <cuda_runtime.h>
#include <math.h>

#define N_ATOMS 10000
#define N_EDGES 256000
#define FDIM    128
#define NRBF_K  20
#define NLAYERS 3
#define NMOLS   100
#define NF      (N_ATOMS*FDIM)          // 1,280,000
#define PHI_D   (3*FDIM)                // 384
#define CUT_R   5.0f
#define EPS_F   1e-8f
#define PI_F    3.14159265358979323846f

// ---------------- scratch (device globals; no allocations allowed) ----------
__device__ float g_rbf [N_EDGES*NRBF_K];
__device__ float g_unit[N_EDGES*3];
__device__ float g_fcut[N_EDGES];
__device__ float g_s1  [NF];
__device__ float g_s2  [NF];
__device__ float g_v1  [3*NF];
__device__ float g_v2  [3*NF];
__device__ float g_phi [N_ATOMS*PHI_D];
__device__ float g_hid [N_ATOMS*FDIM];
__device__ float g_cat [N_ATOMS*2*FDIM];
__device__ float g_uv  [3*NF];
__device__ float g_vv  [3*NF];
__device__ float g_aw  [N_ATOMS*PHI_D];

// ---------------- small elementwise kernels ---------------------------------
__global__ void k_zero(float* p, int n) {
    int i = blockIdx.x*blockDim.x + threadIdx.x;
    if (i < n) p[i] = 0.f;
}
__global__ void k_copy(float* dst, const float* src, int n) {
    int i = blockIdx.x*blockDim.x + threadIdx.x;
    if (i < n) dst[i] = src[i];
}
__global__ void k_init_s(const float* __restrict__ emb, const int* __restrict__ z,
                         float* __restrict__ s) {
    int i = blockIdx.x*blockDim.x + threadIdx.x;
    if (i >= NF) return;
    int n = i >> 7, f = i & 127;
    s[i] = emb[z[n]*FDIM + f];
}

// ---------------- per-edge geometry -----------------------------------------
__global__ void k_geom(const float* __restrict__ xyz, const int* __restrict__ nbrs) {
    int e = blockIdx.x*blockDim.x + threadIdx.x;
    if (e >= N_EDGES) return;
    int i = nbrs[2*e], j = nbrs[2*e+1];
    float dx = xyz[3*j+0] - xyz[3*i+0];
    float dy = xyz[3*j+1] - xyz[3*i+1];
    float dz = xyz[3*j+2] - xyz[3*i+2];
    float d  = sqrtf(dx*dx + dy*dy + dz*dz + EPS_F);
    float inv = 1.0f / d;
    g_unit[3*e+0] = dx*inv;
    g_unit[3*e+1] = dy*inv;
    g_unit[3*e+2] = dz*inv;
    g_fcut[e] = (d < CUT_R) ? 0.5f*(cosf(PI_F*d/CUT_R) + 1.0f) : 0.0f;
    float base = PI_F * d / CUT_R;
    #pragma unroll
    for (int k = 0; k < NRBF_K; k++)
        g_rbf[e*NRBF_K + k] = sinf(base*(float)(k+1)) * inv;
}

// ---------------- SGEMM: C[M,N] = act(A[M,K] @ B[K,N] + bias) ---------------
// BM=128, BN=64, BK=16, 256 threads, 8x4 microtile.
template<bool SILU, bool BIAS>
__global__ void k_sgemm(const float* __restrict__ A, const float* __restrict__ B,
                        const float* __restrict__ bias, float* __restrict__ C,
                        int M, int Nn, int K) {
    __shared__ float As[16][132];   // padded, transposed: As[k][m]
    __shared__ float Bs[16][64];
    const int t  = threadIdx.x;
    const int tn = t & 15;          // col group (4 cols)
    const int tm = t >> 4;          // row group (8 rows)
    const int row0 = blockIdx.y * 128;
    const int col0 = blockIdx.x * 64;

    float acc[8][4];
    #pragma unroll
    for (int i = 0; i < 8; i++)
        #pragma unroll
        for (int j = 0; j < 4; j++) acc[i][j] = 0.f;

    for (int k0 = 0; k0 < K; k0 += 16) {
        // load A tile (128x16) as float4, store transposed
        #pragma unroll
        for (int u = 0; u < 2; u++) {
            int idx = t + u*256;        // 0..511 float4 slots
            int row = idx >> 2;
            int kq  = idx & 3;
            float4 val = make_float4(0.f, 0.f, 0.f, 0.f);
            int gr = row0 + row;
            if (gr < M)
                val = *(const float4*)(A + (size_t)gr*K + k0 + kq*4);
            As[kq*4+0][row] = val.x;
            As[kq*4+1][row] = val.y;
            As[kq*4+2][row] = val.z;
            As[kq*4+3][row] = val.w;
        }
        // load B tile (16x64)
        {
            int kr = t >> 4;
            int cq = t & 15;
            float4 val = *(const float4*)(B + (size_t)(k0+kr)*Nn + col0 + cq*4);
            *(float4*)&Bs[kr][cq*4] = val;
        }
        __syncthreads();
        #pragma unroll
        for (int k = 0; k < 16; k++) {
            float a[8], b[4];
            #pragma unroll
            for (int i = 0; i < 8; i++) a[i] = As[k][tm*8 + i];
            #pragma unroll
            for (int j = 0; j < 4; j++) b[j] = Bs[k][tn*4 + j];
            #pragma unroll
            for (int i = 0; i < 8; i++)
                #pragma unroll
                for (int j = 0; j < 4; j++)
                    acc[i][j] = fmaf(a[i], b[j], acc[i][j]);
        }
        __syncthreads();
    }
    #pragma unroll
    for (int i = 0; i < 8; i++) {
        int gr = row0 + tm*8 + i;
        if (gr < M) {
            float* crow = C + (size_t)gr*Nn + col0 + tn*4;
            #pragma unroll
            for (int j = 0; j < 4; j++) {
                float c = acc[i][j];
                if (BIAS) c += bias[col0 + tn*4 + j];
                if (SILU) c = c / (1.0f + __expf(-c));
                crow[j] = c;
            }
        }
    }
}

// ---------------- edge message kernel ----------------------------------------
// block = 128 threads (one per feature f), 64 edges per block (E = 4000*64).
// dist_W columns for this thread's 3 outputs are held in registers for the
// whole block; rbf/unit/fcut staged in smem; phi[j], v[j] gathered from L2;
// scatter via atomicAdd into the s2/v2 copies.
__global__ void __launch_bounds__(128) k_edge(
        const int*   __restrict__ nbrs,
        const float* __restrict__ dW,     // [20][384] for this layer
        const float* __restrict__ db,     // [384]
        const float* __restrict__ phi,    // [N][384]
        const float* __restrict__ vin,    // [3][N][128] (old v)
        float* __restrict__ sacc,         // [N][128]
        float* __restrict__ vacc)         // [3][N][128]
{
    const int f  = threadIdx.x;
    const int e0 = blockIdx.x * 64;

    __shared__ float s_rbf [64*NRBF_K];
    __shared__ float s_unit[64*3];
    __shared__ float s_fcut[64];
    __shared__ int   s_ij  [128];

    for (int idx = f; idx < 64*NRBF_K; idx += 128) s_rbf[idx]  = g_rbf[e0*NRBF_K + idx];
    for (int idx = f; idx < 192;       idx += 128) s_unit[idx] = g_unit[e0*3 + idx];
    if (f < 64) s_fcut[f] = g_fcut[e0 + f];
    s_ij[f] = nbrs[e0*2 + f];

    float wA[NRBF_K], wB[NRBF_K], wC[NRBF_K];
    #pragma unroll
    for (int k = 0; k < NRBF_K; k++) {
        wA[k] = dW[k*PHI_D + f];
        wB[k] = dW[k*PHI_D + 128 + f];
        wC[k] = dW[k*PHI_D + 256 + f];
    }
    const float bA = db[f], bB = db[128+f], bC = db[256+f];
    __syncthreads();

    for (int e = 0; e < 64; e++) {
        const int i  = s_ij[2*e];
        const int j  = s_ij[2*e+1];
        const float fc = s_fcut[e];
        float w0 = bA, w1 = bB, w2 = bC;
        #pragma unroll
        for (int k = 0; k < NRBF_K; k++) {
            const float r = s_rbf[e*NRBF_K + k];
            w0 = fmaf(r, wA[k], w0);
            w1 = fmaf(r, wB[k], w1);
            w2 = fmaf(r, wC[k], w2);
        }
        w0 *= fc; w1 *= fc; w2 *= fc;

        const float* pj = phi + (size_t)j*PHI_D;
        const float inv0 = pj[f]       * w0;
        const float inv1 = pj[128 + f] * w1;
        const float inv2 = pj[256 + f] * w2;

        atomicAdd(&sacc[(size_t)i*FDIM + f], inv0);

        const float u0 = s_unit[3*e+0], u1 = s_unit[3*e+1], u2 = s_unit[3*e+2];
        const float* vj = vin  + (size_t)j*FDIM + f;
        float*       va = vacc + (size_t)i*FDIM + f;
        atomicAdd(&va[0],    fmaf(inv1, vj[0],    inv2*u0));
        atomicAdd(&va[NF],   fmaf(inv1, vj[NF],   inv2*u1));
        atomicAdd(&va[2*NF], fmaf(inv1, vj[2*NF], inv2*u2));
    }
}

// ---------------- update-phase elementwise kernels ---------------------------
__global__ void k_cat(const float* __restrict__ s2, const float* __restrict__ vv,
                      float* __restrict__ cat) {
    int idx = blockIdx.x*blockDim.x + threadIdx.x;
    if (idx >= NF) return;
    int n = idx >> 7, g = idx & 127;
    float w0 = vv[idx], w1 = vv[idx + NF], w2 = vv[idx + 2*NF];
    cat[n*256 + g]       = s2[idx];
    cat[n*256 + 128 + g] = sqrtf(w0*w0 + w1*w1 + w2*w2 + EPS_F);
}

__global__ void k_combine(const float* __restrict__ s2, const float* __restrict__ v2,
                          const float* __restrict__ uv, const float* __restrict__ vv,
                          const float* __restrict__ aw,
                          float* __restrict__ sOut, float* __restrict__ vOut) {
    int idx = blockIdx.x*blockDim.x + threadIdx.x;
    if (idx >= NF) return;
    int n = idx >> 7, f = idx & 127;
    float a0 = aw[(size_t)n*PHI_D + f];
    float a1 = aw[(size_t)n*PHI_D + 128 + f];
    float a2 = aw[(size_t)n*PHI_D + 256 + f];
    float u0 = uv[idx], u1 = uv[idx + NF], u2 = uv[idx + 2*NF];
    float w0 = vv[idx], w1 = vv[idx + NF], w2 = vv[idx + 2*NF];
    float dot = u0*w0 + u1*w1 + u2*w2;
    sOut[idx]        = s2[idx] + a1*dot + a2;
    vOut[idx]        = v2[idx]        + u0*a0;
    vOut[idx + NF]   = v2[idx + NF]   + u1*a0;
    vOut[idx + 2*NF] = v2[idx + 2*NF] + u2*a0;
}

// ---------------- readout ----------------------------------------------------
__global__ void k_readout(const float* __restrict__ hid, const float* __restrict__ W2,
                          const float* __restrict__ b2, const int* __restrict__ mol,
                          float* __restrict__ out) {
    int n = blockIdx.x*blockDim.x + threadIdx.x;
    if (n >= N_ATOMS) return;
    float acc = b2[0];
    const float* h = hid + (size_t)n*64;
    #pragma unroll
    for (int k = 0; k < 64; k++) acc = fmaf(h[k], W2[k], acc);
    atomicAdd(&out[mol[n]], acc);
}

// ---------------- host-side orchestration ------------------------------------
extern "C" void kernel_launch(void* const* d_in, const int* in_sizes, int n_in,
                              void* d_out, int out_size) {
    const float* xyz    = (const float*)d_in[0];
    const int*   z      = (const int*)  d_in[1];
    const int*   nbrs   = (const int*)  d_in[2];
    const int*   mol    = (const int*)  d_in[3];
    const float* emb    = (const float*)d_in[4];
    const float* msgW1  = (const float*)d_in[5];
    const float* msgb1  = (const float*)d_in[6];
    const float* msgW2  = (const float*)d_in[7];
    const float* msgb2  = (const float*)d_in[8];
    const float* distW  = (const float*)d_in[9];
    const float* distb  = (const float*)d_in[10];
    const float* updU   = (const float*)d_in[11];
    const float* updV   = (const float*)d_in[12];
    const float* updW1  = (const float*)d_in[13];
    const float* updb1  = (const float*)d_in[14];
    const float* updW2  = (const float*)d_in[15];
    const float* updb2  = (const float*)d_in[16];
    const float* readW1 = (const float*)d_in[17];
    const float* readb1 = (const float*)d_in[18];
    const float* readW2 = (const float*)d_in[19];
    const float* readb2 = (const float*)d_in[20];
    float* out = (float*)d_out;

    float *s1, *s2, *v1, *v2, *phi, *hid, *cat, *uv, *vv, *aw;
    cudaGetSymbolAddress((void**)&s1,  g_s1);
    cudaGetSymbolAddress((void**)&s2,  g_s2);
    cudaGetSymbolAddress((void**)&v1,  g_v1);
    cudaGetSymbolAddress((void**)&v2,  g_v2);
    cudaGetSymbolAddress((void**)&phi, g_phi);
    cudaGetSymbolAddress((void**)&hid, g_hid);
    cudaGetSymbolAddress((void**)&cat, g_cat);
    cudaGetSymbolAddress((void**)&uv,  g_uv);
    cudaGetSymbolAddress((void**)&vv,  g_vv);
    cudaGetSymbolAddress((void**)&aw,  g_aw);

    const int TPB = 256;
    // init: s = emb[z], v = 0
    k_init_s<<<(NF + TPB - 1)/TPB, TPB>>>(emb, z, s1);
    k_zero  <<<(3*NF + TPB - 1)/TPB, TPB>>>(v1, 3*NF);
    // edge geometry (layer-invariant)
    k_geom  <<<(N_EDGES + TPB - 1)/TPB, TPB>>>(xyz, nbrs);

    const dim3 gN128(1, (N_ATOMS + 127)/128);   // unused placeholder dims below
    for (int l = 0; l < NLAYERS; l++) {
        const float* mW1 = msgW1 + (size_t)l*128*128;
        const float* mb1 = msgb1 + (size_t)l*128;
        const float* mW2 = msgW2 + (size_t)l*128*384;
        const float* mb2 = msgb2 + (size_t)l*384;
        const float* dW  = distW + (size_t)l*NRBF_K*384;
        const float* dbv = distb + (size_t)l*384;
        const float* uU  = updU  + (size_t)l*128*128;
        const float* uV  = updV  + (size_t)l*128*128;
        const float* uW1 = updW1 + (size_t)l*256*128;
        const float* ub1 = updb1 + (size_t)l*128;
        const float* uW2 = updW2 + (size_t)l*128*384;
        const float* ub2 = updb2 + (size_t)l*384;

        // phi = silu(s@W1 + b1)@W2 + b2
        k_sgemm<true,  true><<<dim3(2, 79), 256>>>(s1,  mW1, mb1, hid, N_ATOMS, 128, 128);
        k_sgemm<false, true><<<dim3(6, 79), 256>>>(hid, mW2, mb2, phi, N_ATOMS, 384, 128);

        // accumulate edges into copies of s, v
        k_copy<<<(NF   + TPB - 1)/TPB, TPB>>>(s2, s1, NF);
        k_copy<<<(3*NF + TPB - 1)/TPB, TPB>>>(v2, v1, 3*NF);
        k_edge<<<N_EDGES/64, 128>>>(nbrs, dW, dbv, phi, v1, s2, v2);

        // update phase
        k_sgemm<false, false><<<dim3(2, 235), 256>>>(v2, uU, (const float*)nullptr, uv, 3*N_ATOMS, 128, 128);
        k_sgemm<false, false><<<dim3(2, 235), 256>>>(v2, uV, (const float*)nullptr, vv, 3*N_ATOMS, 128, 128);
        k_cat<<<(NF + TPB - 1)/TPB, TPB>>>(s2, vv, cat);
        k_sgemm<true,  true><<<dim3(2, 79), 256>>>(cat, uW1, ub1, hid, N_ATOMS, 128, 256);
        k_sgemm<false, true><<<dim3(6, 79), 256>>>(hid, uW2, ub2, aw,  N_ATOMS, 384, 128);
        k_combine<<<(NF + TPB - 1)/TPB, TPB>>>(s2, v2, uv, vv, aw, s1, v1);
    }

    // readout
    k_sgemm<true, true><<<dim3(1, 79), 256>>>(s1, readW1, readb1, hid, N_ATOMS, 64, 128);
    k_zero<<<1, 128>>>(out, NMOLS);
    k_readout<<<(N_ATOMS + TPB - 1)/TPB, TPB>>>(hid, readW2, readb2, mol, out);
}

// round 2
// speedup vs baseline: 1.3905x; 1.3905x over previous
#include <cuda_runtime.h>
#include <math.h>

#define NA      10000
#define NE      256000
#define FDIM    128
#define NRBF_K  20
#define NLAYERS 3
#define NMOLS   100
#define NF      (NA*FDIM)               // 1,280,000
#define PHI_D   384
#define CUT_R   5.0f
#define EPS_F   1e-8f
#define PI_F    3.14159265358979323846f

// ---------------- scratch (device globals; no allocations allowed) ----------
__device__ float g_rbfs[NE*NRBF_K];     // rbf * fcut, CSR-sorted
__device__ float g_unit[NE*3];          // CSR-sorted
__device__ float g_fc  [NE];            // fcut, CSR-sorted
__device__ int   g_sj  [NE];            // j per CSR slot
__device__ int   g_perm[NE];            // edge -> CSR slot
__device__ int   g_cnt [NA];
__device__ int   g_roff[NA+1];
__device__ int   g_cur [NA];
__device__ float g_s1  [NF];
__device__ float g_s2  [NF];
__device__ float g_v1  [3*NF];
__device__ float g_v2  [3*NF];
__device__ float g_phi [NA*PHI_D];
__device__ float g_hid [NF];
__device__ float g_cat [NA*2*FDIM];
__device__ float g_uvvv[(size_t)3*NA*256];
__device__ float g_aw  [NA*PHI_D];
__device__ float g_Bcat[NLAYERS*FDIM*256];   // [l][k][ U(0..127) | V(128..255) ]

// ---------------- CSR build --------------------------------------------------
__global__ void k_count(const int* __restrict__ nbrs) {
    int e = blockIdx.x*blockDim.x + threadIdx.x;
    if (e < NE) atomicAdd(&g_cnt[nbrs[2*e]], 1);
}

__global__ void k_scan() {
    __shared__ int sh[1024];
    __shared__ int carry;
    const int tid = threadIdx.x;
    if (tid == 0) carry = 0;
    __syncthreads();
    for (int base = 0; base < NA; base += 1024) {
        int idx = base + tid;
        int v = (idx < NA) ? g_cnt[idx] : 0;
        sh[tid] = v; __syncthreads();
        #pragma unroll
        for (int off = 1; off < 1024; off <<= 1) {
            int t = (tid >= off) ? sh[tid-off] : 0;
            __syncthreads();
            sh[tid] += t;
            __syncthreads();
        }
        if (idx < NA) g_roff[idx] = carry + sh[tid] - v;
        int tot = sh[1023];
        __syncthreads();
        if (tid == 0) carry += tot;
        __syncthreads();
    }
    if (tid == 0) g_roff[NA] = carry;
}

__global__ void k_fill(const int* __restrict__ nbrs) {
    int e = blockIdx.x*blockDim.x + threadIdx.x;
    if (e >= NE) return;
    int i = nbrs[2*e];
    int slot = atomicAdd(&g_cur[i], 1);
    g_perm[e] = slot;
    g_sj[slot] = nbrs[2*e+1];
}

// ---------------- concat U|V into Bcat (once) --------------------------------
__global__ void k_catUV(const float* __restrict__ U, const float* __restrict__ V) {
    int idx = blockIdx.x*blockDim.x + threadIdx.x;
    if (idx >= NLAYERS*FDIM*256) return;
    int l = idx >> 15;           // /32768
    int rem = idx & 32767;
    int k = rem >> 8, g = rem & 255;
    g_Bcat[idx] = (g < 128) ? U[l*16384 + k*128 + g] : V[l*16384 + k*128 + g - 128];
}

// ---------------- fused init (s=emb[z], v=0) + per-edge geometry -------------
__global__ void k_prepgeom(const float* __restrict__ xyz, const int* __restrict__ nbrs,
                           const int* __restrict__ z, const float* __restrict__ emb) {
    int t = blockIdx.x*blockDim.x + threadIdx.x;
    if (t >= NF) return;
    // s/v init
    {
        int n = t >> 7, f = t & 127;
        g_s1[t] = emb[z[n]*FDIM + f];
        g_v1[t] = 0.f; g_v1[t + NF] = 0.f; g_v1[t + 2*NF] = 0.f;
    }
    // geometry (CSR-ordered writes)
    if (t < NE) {
        int e = t;
        int i = nbrs[2*e], j = nbrs[2*e+1];
        float dx = xyz[3*j+0] - xyz[3*i+0];
        float dy = xyz[3*j+1] - xyz[3*i+1];
        float dz = xyz[3*j+2] - xyz[3*i+2];
        float d  = sqrtf(dx*dx + dy*dy + dz*dz + EPS_F);
        float inv = 1.0f / d;
        float fc = (d < CUT_R) ? 0.5f*(cosf(PI_F*d*(1.0f/CUT_R)) + 1.0f) : 0.0f;
        int slot = g_perm[e];
        g_unit[3*slot+0] = dx*inv;
        g_unit[3*slot+1] = dy*inv;
        g_unit[3*slot+2] = dz*inv;
        g_fc[slot] = fc;
        float base = PI_F * d * (1.0f/CUT_R);
        float sc = inv * fc;
        #pragma unroll
        for (int k = 0; k < NRBF_K; k++)
            g_rbfs[slot*NRBF_K + k] = sinf(base*(float)(k+1)) * sc;
    }
}

// ---------------- GEMM: C[M,N] = act(A[M,K] @ B[K,N] + bias) -----------------
// BM=64, BK=16, 256 threads, 4xTN microtile, smem ping-pong double buffer.
template<int BN, bool SILU, bool BIAS>
__global__ void __launch_bounds__(256) k_gemm(
        const float* __restrict__ A, const float* __restrict__ B,
        const float* __restrict__ bias, float* __restrict__ C,
        int M, int Nn, int K)
{
    constexpr int TN  = BN/16;        // 8 or 4
    constexpr int NB4 = BN/64;        // B float4 loads per thread (2 or 1)
    constexpr int B4  = BN/4;
    __shared__ float As[2][16][68];
    __shared__ float Bs[2][16][BN];
    const int t  = threadIdx.x;
    const int tx = t & 15, ty = t >> 4;
    const int row0 = blockIdx.y*64, col0 = blockIdx.x*BN;
    const int arow = t >> 2, akq = t & 3;
    const int gr = row0 + arow;
    const bool aok = (gr < M);
    const float* Aptr = A + (size_t)gr*K + akq*4;

    float acc[4][TN];
    #pragma unroll
    for (int i = 0; i < 4; i++)
        #pragma unroll
        for (int j = 0; j < TN; j++) acc[i][j] = 0.f;

    const int NT = K/16;
    // prologue: tile 0 -> smem[0]
    {
        float4 va = aok ? *(const float4*)Aptr : make_float4(0,0,0,0);
        As[0][akq*4+0][arow] = va.x; As[0][akq*4+1][arow] = va.y;
        As[0][akq*4+2][arow] = va.z; As[0][akq*4+3][arow] = va.w;
        #pragma unroll
        for (int u = 0; u < NB4; u++) {
            int slot = t + u*256, br = slot/B4, bc = slot%B4;
            *(float4*)&Bs[0][br][bc*4] = *(const float4*)(B + (size_t)br*Nn + col0 + bc*4);
        }
    }
    __syncthreads();

    for (int kt = 0; kt < NT; kt++) {
        const int buf = kt & 1;
        const bool more = (kt+1 < NT);
        float4 na = make_float4(0,0,0,0);
        float4 nb[NB4];
        if (more) {
            if (aok) na = *(const float4*)(Aptr + (kt+1)*16);
            #pragma unroll
            for (int u = 0; u < NB4; u++) {
                int slot = t + u*256, br = slot/B4, bc = slot%B4;
                nb[u] = *(const float4*)(B + (size_t)((kt+1)*16 + br)*Nn + col0 + bc*4);
            }
        }
        #pragma unroll
        for (int k = 0; k < 16; k++) {
            const float4 av = *(const float4*)&As[buf][k][ty*4];
            const float4 b0 = *(const float4*)&Bs[buf][k][tx*4];
            float a_[4] = {av.x, av.y, av.z, av.w};
            float b_[TN];
            b_[0]=b0.x; b_[1]=b0.y; b_[2]=b0.z; b_[3]=b0.w;
            if constexpr (TN == 8) {
                const float4 b1 = *(const float4*)&Bs[buf][k][64 + tx*4];
                b_[4]=b1.x; b_[5]=b1.y; b_[6]=b1.z; b_[7]=b1.w;
            }
            #pragma unroll
            for (int i = 0; i < 4; i++)
                #pragma unroll
                for (int j = 0; j < TN; j++)
                    acc[i][j] = fmaf(a_[i], b_[j], acc[i][j]);
        }
        if (more) {
            const int nbuf = buf ^ 1;
            As[nbuf][akq*4+0][arow] = na.x; As[nbuf][akq*4+1][arow] = na.y;
            As[nbuf][akq*4+2][arow] = na.z; As[nbuf][akq*4+3][arow] = na.w;
            #pragma unroll
            for (int u = 0; u < NB4; u++) {
                int slot = t + u*256, br = slot/B4, bc = slot%B4;
                *(float4*)&Bs[nbuf][br][bc*4] = nb[u];
            }
        }
        __syncthreads();
    }

    // epilogue
    float4 bb0 = make_float4(0,0,0,0), bb1 = make_float4(0,0,0,0);
    if (BIAS) {
        bb0 = *(const float4*)(bias + col0 + tx*4);
        if constexpr (TN == 8) bb1 = *(const float4*)(bias + col0 + 64 + tx*4);
    }
    #pragma unroll
    for (int i = 0; i < 4; i++) {
        int r = row0 + ty*4 + i;
        if (r >= M) continue;
        float o[TN];
        #pragma unroll
        for (int j = 0; j < TN; j++) o[j] = acc[i][j];
        if (BIAS) {
            o[0]+=bb0.x; o[1]+=bb0.y; o[2]+=bb0.z; o[3]+=bb0.w;
            if constexpr (TN == 8) { o[4]+=bb1.x; o[5]+=bb1.y; o[6]+=bb1.z; o[7]+=bb1.w; }
        }
        if (SILU) {
            #pragma unroll
            for (int j = 0; j < TN; j++) o[j] = o[j] / (1.0f + __expf(-o[j]));
        }
        float* cp = C + (size_t)r*Nn + col0;
        *(float4*)(cp + tx*4) = make_float4(o[0], o[1], o[2], o[3]);
        if constexpr (TN == 8)
            *(float4*)(cp + 64 + tx*4) = make_float4(o[4], o[5], o[6], o[7]);
    }
}

// ---------------- CSR edge kernel (no atomics) -------------------------------
// block = 128 threads (one per feature f), one atom per block.
__global__ void __launch_bounds__(128) k_edge(
        const float* __restrict__ dW,     // [20][384]
        const float* __restrict__ db,     // [384]
        const float* __restrict__ phi,    // [N][384]
        const float* __restrict__ s1,
        const float* __restrict__ v1,     // [3][N][128]
        float* __restrict__ s2,
        float* __restrict__ v2)
{
    const int i = blockIdx.x, f = threadIdx.x;
    __shared__ float s_rbf [32*NRBF_K];
    __shared__ float s_unit[32*3];
    __shared__ float s_fc  [32];
    __shared__ int   s_jj  [32];

    float wA[NRBF_K], wB[NRBF_K], wC[NRBF_K];
    #pragma unroll
    for (int k = 0; k < NRBF_K; k++) {
        wA[k] = dW[k*PHI_D + f];
        wB[k] = dW[k*PHI_D + 128 + f];
        wC[k] = dW[k*PHI_D + 256 + f];
    }
    const float bA = db[f], bB = db[128+f], bC = db[256+f];
    const int r0 = g_roff[i], r1 = g_roff[i+1];

    float accS = 0.f, aV0 = 0.f, aV1 = 0.f, aV2 = 0.f;
    for (int base = r0; base < r1; base += 32) {
        const int cnt = min(32, r1 - base);
        __syncthreads();
        for (int idx = f; idx < cnt*NRBF_K; idx += 128) s_rbf[idx]  = g_rbfs[base*NRBF_K + idx];
        for (int idx = f; idx < cnt*3;      idx += 128) s_unit[idx] = g_unit[base*3 + idx];
        if (f < cnt) { s_fc[f] = g_fc[base+f]; s_jj[f] = g_sj[base+f]; }
        __syncthreads();
        for (int t = 0; t < cnt; t++) {
            const float fcv = s_fc[t];
            float w0 = fcv*bA, w1 = fcv*bB, w2 = fcv*bC;
            #pragma unroll
            for (int k = 0; k < NRBF_K; k++) {
                const float r = s_rbf[t*NRBF_K + k];
                w0 = fmaf(r, wA[k], w0);
                w1 = fmaf(r, wB[k], w1);
                w2 = fmaf(r, wC[k], w2);
            }
            const int j = s_jj[t];
            const float* pj = phi + (size_t)j*PHI_D;
            const float i0 = pj[f]*w0, i1 = pj[128+f]*w1, i2 = pj[256+f]*w2;
            accS += i0;
            const float* vj = v1 + (size_t)j*FDIM + f;
            aV0 = fmaf(i1, vj[0],    fmaf(i2, s_unit[t*3+0], aV0));
            aV1 = fmaf(i1, vj[NF],   fmaf(i2, s_unit[t*3+1], aV1));
            aV2 = fmaf(i1, vj[2*NF], fmaf(i2, s_unit[t*3+2], aV2));
        }
    }
    const size_t o = (size_t)i*FDIM + f;
    s2[o]        = s1[o]        + accS;
    v2[o]        = v1[o]        + aV0;
    v2[o + NF]   = v1[o + NF]   + aV1;
    v2[o + 2*NF] = v1[o + 2*NF] + aV2;
}

// ---------------- update-phase elementwise kernels ---------------------------
__global__ void k_cat(const float* __restrict__ s2, const float* __restrict__ uvvv,
                      float* __restrict__ cat) {
    int idx = blockIdx.x*blockDim.x + threadIdx.x;
    if (idx >= NF) return;
    int n = idx >> 7, g = idx & 127;
    float w0 = uvvv[((size_t)(0*NA+n))*256 + 128 + g];
    float w1 = uvvv[((size_t)(1*NA+n))*256 + 128 + g];
    float w2 = uvvv[((size_t)(2*NA+n))*256 + 128 + g];
    cat[n*256 + g]       = s2[idx];
    cat[n*256 + 128 + g] = sqrtf(w0*w0 + w1*w1 + w2*w2 + EPS_F);
}

__global__ void k_combine(const float* __restrict__ s2, const float* __restrict__ v2,
                          const float* __restrict__ uvvv, const float* __restrict__ aw,
                          float* __restrict__ sOut, float* __restrict__ vOut) {
    int idx = blockIdx.x*blockDim.x + threadIdx.x;
    if (idx >= NF) return;
    int n = idx >> 7, f = idx & 127;
    float a0 = aw[(size_t)n*PHI_D + f];
    float a1 = aw[(size_t)n*PHI_D + 128 + f];
    float a2 = aw[(size_t)n*PHI_D + 256 + f];
    float u0 = uvvv[((size_t)(0*NA+n))*256 + f];
    float u1 = uvvv[((size_t)(1*NA+n))*256 + f];
    float u2 = uvvv[((size_t)(2*NA+n))*256 + f];
    float w0 = uvvv[((size_t)(0*NA+n))*256 + 128 + f];
    float w1 = uvvv[((size_t)(1*NA+n))*256 + 128 + f];
    float w2 = uvvv[((size_t)(2*NA+n))*256 + 128 + f];
    float dot = u0*w0 + u1*w1 + u2*w2;
    sOut[idx]        = s2[idx] + a1*dot + a2;
    vOut[idx]        = v2[idx]        + u0*a0;
    vOut[idx + NF]   = v2[idx + NF]   + u1*a0;
    vOut[idx + 2*NF] = v2[idx + 2*NF] + u2*a0;
}

// ---------------- readout ----------------------------------------------------
__global__ void k_readout(const float* __restrict__ hid, const float* __restrict__ W2,
                          const float* __restrict__ b2, const int* __restrict__ mol,
                          float* __restrict__ out) {
    int n = blockIdx.x*blockDim.x + threadIdx.x;
    if (n >= NA) return;
    float acc = b2[0];
    const float* h = hid + (size_t)n*64;
    #pragma unroll
    for (int k = 0; k < 64; k++) acc = fmaf(h[k], W2[k], acc);
    atomicAdd(&out[mol[n]], acc);
}

// ---------------- host-side orchestration ------------------------------------
extern "C" void kernel_launch(void* const* d_in, const int* in_sizes, int n_in,
                              void* d_out, int out_size) {
    const float* xyz    = (const float*)d_in[0];
    const int*   z      = (const int*)  d_in[1];
    const int*   nbrs   = (const int*)  d_in[2];
    const int*   mol    = (const int*)  d_in[3];
    const float* emb    = (const float*)d_in[4];
    const float* msgW1  = (const float*)d_in[5];
    const float* msgb1  = (const float*)d_in[6];
    const float* msgW2  = (const float*)d_in[7];
    const float* msgb2  = (const float*)d_in[8];
    const float* distW  = (const float*)d_in[9];
    const float* distb  = (const float*)d_in[10];
    const float* updU   = (const float*)d_in[11];
    const float* updV   = (const float*)d_in[12];
    const float* updW1  = (const float*)d_in[13];
    const float* updb1  = (const float*)d_in[14];
    const float* updW2  = (const float*)d_in[15];
    const float* updb2  = (const float*)d_in[16];
    const float* readW1 = (const float*)d_in[17];
    const float* readb1 = (const float*)d_in[18];
    const float* readW2 = (const float*)d_in[19];
    const float* readb2 = (const float*)d_in[20];
    float* out = (float*)d_out;

    float *s1, *s2, *v1, *v2, *phi, *hid, *cat, *uvvv, *aw, *Bcat;
    int *cnt, *roff, *cur;
    cudaGetSymbolAddress((void**)&s1,   g_s1);
    cudaGetSymbolAddress((void**)&s2,   g_s2);
    cudaGetSymbolAddress((void**)&v1,   g_v1);
    cudaGetSymbolAddress((void**)&v2,   g_v2);
    cudaGetSymbolAddress((void**)&phi,  g_phi);
    cudaGetSymbolAddress((void**)&hid,  g_hid);
    cudaGetSymbolAddress((void**)&cat,  g_cat);
    cudaGetSymbolAddress((void**)&uvvv, g_uvvv);
    cudaGetSymbolAddress((void**)&aw,   g_aw);
    cudaGetSymbolAddress((void**)&Bcat, g_Bcat);
    cudaGetSymbolAddress((void**)&cnt,  g_cnt);
    cudaGetSymbolAddress((void**)&roff, g_roff);
    cudaGetSymbolAddress((void**)&cur,  g_cur);

    const int TPB = 256;
    // ---- CSR build (reused across all layers) ----
    cudaMemsetAsync(cnt, 0, NA*sizeof(int));
    k_count<<<NE/TPB, TPB>>>(nbrs);                      // kernel 1
    k_scan <<<1, 1024>>>();                              // kernel 2
    cudaMemcpyAsync(cur, roff, NA*sizeof(int), cudaMemcpyDeviceToDevice);
    k_fill <<<NE/TPB, TPB>>>(nbrs);                      // kernel 3
    k_catUV<<<(NLAYERS*FDIM*256 + TPB-1)/TPB, TPB>>>(updU, updV);   // kernel 4
    k_prepgeom<<<NF/TPB, TPB>>>(xyz, nbrs, z, emb);      // kernel 5

    const int GY1 = (NA + 63)/64;       // 157
    const int GY3 = (3*NA + 63)/64;     // 469
    for (int l = 0; l < NLAYERS; l++) {
        const float* mW1 = msgW1 + (size_t)l*128*128;
        const float* mb1 = msgb1 + (size_t)l*128;
        const float* mW2 = msgW2 + (size_t)l*128*384;
        const float* mb2 = msgb2 + (size_t)l*384;
        const float* dW  = distW + (size_t)l*NRBF_K*384;
        const float* dbv = distb + (size_t)l*384;
        const float* uW1 = updW1 + (size_t)l*256*128;
        const float* ub1 = updb1 + (size_t)l*128;
        const float* uW2 = updW2 + (size_t)l*128*384;
        const float* ub2 = updb2 + (size_t)l*384;
        const float* Bc  = Bcat  + (size_t)l*128*256;

        // phi = silu(s@W1 + b1)@W2 + b2
        k_gemm<128, true,  true><<<dim3(1, GY1), 256>>>(s1,  mW1, mb1, hid, NA, 128, 128);   // kernel 6 (profiled)
        k_gemm<128, false, true><<<dim3(3, GY1), 256>>>(hid, mW2, mb2, phi, NA, 384, 128);
        // edge aggregation (CSR, no atomics): s2 = s1 + ds, v2 = v1 + dv
        k_edge<<<NA, 128>>>(dW, dbv, phi, s1, v1, s2, v2);
        // update phase: [uv | vv] in one GEMM (N=256)
        k_gemm<128, false, false><<<dim3(2, GY3), 256>>>(v2, Bc, (const float*)nullptr, uvvv, 3*NA, 256, 128);
        k_cat<<<NF/TPB, TPB>>>(s2, uvvv, cat);
        k_gemm<128, true,  true><<<dim3(1, GY1), 256>>>(cat, uW1, ub1, hid, NA, 128, 256);
        k_gemm<128, false, true><<<dim3(3, GY1), 256>>>(hid, uW2, ub2, aw,  NA, 384, 128);
        k_combine<<<NF/TPB, TPB>>>(s2, v2, uvvv, aw, s1, v1);
    }

    // readout
    k_gemm<64, true, true><<<dim3(1, GY1), 256>>>(s1, readW1, readb1, hid, NA, 64, 128);
    cudaMemsetAsync(out, 0, NMOLS*sizeof(float));
    k_readout<<<(NA + TPB-1)/TPB, TPB>>>(hid, readW2, readb2, mol, out);
}

// round 4
// speedup vs baseline: 1.7599x; 1.2657x over previous
#include <cuda_runtime.h>
#include <math.h>
#include <stdint.h>

#define NA      10000
#define NE      256000
#define FDIM    128
#define NRBF_K  20
#define NLAYERS 3
#define NMOLS   100
#define NF      (NA*FDIM)               // 1,280,000
#define PHI_D   384
#define CUT_R   5.0f
#define EPS_F   1e-8f
#define PI_F    3.14159265358979323846f

// ---------------- scratch (device globals; no allocations allowed) ----------
__device__ float g_rbfs[NE*NRBF_K];     // rbf * fcut, CSR-sorted
__device__ float g_unit[NE*3];          // CSR-sorted
__device__ float g_fc  [NE];            // fcut, CSR-sorted
__device__ int   g_sj  [NE];            // j per CSR slot
__device__ int   g_perm[NE];            // edge -> CSR slot
__device__ int   g_cnt [NA];
__device__ int   g_roff[NA+1];
__device__ int   g_cur [NA];
__device__ float g_s1  [NF];
__device__ float g_s2  [NF];
__device__ float g_v1  [3*NF];
__device__ float g_v2  [3*NF];
__device__ float g_phi [NA*PHI_D];
__device__ float g_hid [NF];
__device__ float g_cat [NA*2*FDIM];
__device__ float g_uvvv[(size_t)3*NA*256];
__device__ float g_aw  [NA*PHI_D];
__device__ float g_Bcat[NLAYERS*FDIM*256];   // [l][k][ U(0..127) | V(128..255) ]

// ---------------- CSR build --------------------------------------------------
__global__ void k_count(const int* __restrict__ nbrs) {
    int e = blockIdx.x*blockDim.x + threadIdx.x;
    if (e < NE) atomicAdd(&g_cnt[nbrs[2*e]], 1);
}

__global__ void k_scan() {
    __shared__ int sh[1024];
    __shared__ int carry;
    const int tid = threadIdx.x;
    if (tid == 0) carry = 0;
    __syncthreads();
    for (int base = 0; base < NA; base += 1024) {
        int idx = base + tid;
        int v = (idx < NA) ? g_cnt[idx] : 0;
        sh[tid] = v; __syncthreads();
        #pragma unroll
        for (int off = 1; off < 1024; off <<= 1) {
            int t = (tid >= off) ? sh[tid-off] : 0;
            __syncthreads();
            sh[tid] += t;
            __syncthreads();
        }
        if (idx < NA) { int r = carry + sh[tid] - v; g_roff[idx] = r; g_cur[idx] = r; }
        int tot = sh[1023];
        __syncthreads();
        if (tid == 0) carry += tot;
        __syncthreads();
    }
    if (tid == 0) g_roff[NA] = carry;
}

__global__ void k_fill(const int* __restrict__ nbrs) {
    int e = blockIdx.x*blockDim.x + threadIdx.x;
    if (e >= NE) return;
    int i = nbrs[2*e];
    int slot = atomicAdd(&g_cur[i], 1);
    g_perm[e] = slot;
    g_sj[slot] = nbrs[2*e+1];
}

// ---------------- concat U|V into Bcat + zero g_cnt (once) -------------------
__global__ void k_catUV(const float* __restrict__ U, const float* __restrict__ V) {
    int idx = blockIdx.x*blockDim.x + threadIdx.x;
    if (idx < NA) g_cnt[idx] = 0;
    if (idx >= NLAYERS*FDIM*256) return;
    int l = idx >> 15;
    int rem = idx & 32767;
    int k = rem >> 8, g = rem & 255;
    g_Bcat[idx] = (g < 128) ? U[l*16384 + k*128 + g] : V[l*16384 + k*128 + g - 128];
}

// ---------------- fused init (s=emb[z], v=0) + per-edge geometry -------------
__global__ void k_prepgeom(const float* __restrict__ xyz, const int* __restrict__ nbrs,
                           const int* __restrict__ z, const float* __restrict__ emb) {
    int t = blockIdx.x*blockDim.x + threadIdx.x;
    if (t >= NF) return;
    {
        int n = t >> 7, f = t & 127;
        g_s1[t] = emb[z[n]*FDIM + f];
        g_v1[t] = 0.f; g_v1[t + NF] = 0.f; g_v1[t + 2*NF] = 0.f;
    }
    if (t < NE) {
        int e = t;
        int i = nbrs[2*e], j = nbrs[2*e+1];
        float dx = xyz[3*j+0] - xyz[3*i+0];
        float dy = xyz[3*j+1] - xyz[3*i+1];
        float dz = xyz[3*j+2] - xyz[3*i+2];
        float d  = sqrtf(dx*dx + dy*dy + dz*dz + EPS_F);
        float inv = 1.0f / d;
        float fc = (d < CUT_R) ? 0.5f*(cosf(PI_F*d*(1.0f/CUT_R)) + 1.0f) : 0.0f;
        int slot = g_perm[e];
        g_unit[3*slot+0] = dx*inv;
        g_unit[3*slot+1] = dy*inv;
        g_unit[3*slot+2] = dz*inv;
        g_fc[slot] = fc;
        float base = PI_F * d * (1.0f/CUT_R);
        float sc = inv * fc;
        #pragma unroll
        for (int k = 0; k < NRBF_K; k++)
            g_rbfs[slot*NRBF_K + k] = sinf(base*(float)(k+1)) * sc;
    }
}

// ---------------- tf32 tensor-core GEMM --------------------------------------
// C[M,N] = act(A[M,K] @ B[K,N] + bias).  BM=128, BN=64, BK=16.
// 256 threads = 8 warps in 4(m) x 2(n); warp tile 32x32 (2 m16 x 4 n8 mma).
__device__ __forceinline__ float totf(float x) {
    float r; asm("cvt.rna.tf32.f32 %0, %1;" : "=f"(r) : "f"(x)); return r;
}

template<bool SILU, bool BIAS>
__global__ void __launch_bounds__(256) k_tgemm(
        const float* __restrict__ A, const float* __restrict__ B,
        const float* __restrict__ bias, float* __restrict__ C,
        int M, int Nn, int K)
{
    __shared__ float As[2][128][20];    // [m][k], pad 20 (LDS conflict-free)
    __shared__ float Bs[2][16][68];     // [k][n], pad 68
    const int t = threadIdx.x;
    const int lane = t & 31, wid = t >> 5;
    const int wm = wid & 3, wn = wid >> 1 & 2 ? 0 : 0; // placeholder (recomputed below)
    const int warp_m = wid & 3;          // 0..3 -> rows warp_m*32
    const int warp_n = wid >> 2;         // 0..1 -> cols warp_n*32
    (void)wm; (void)wn;
    const int row0 = blockIdx.y*128, col0 = blockIdx.x*64;
    const int g = lane >> 2, tg = lane & 3;   // groupID, thread-in-group

    // A loads: 512 float4 / 256 thr = 2 each. idx -> row=idx>>2, kq=idx&3
    const int ar0 = t >> 2, akq = t & 3;
    // B loads: 256 float4 / 256 thr = 1 each. k=t>>4, n4=t&15
    const int bk = t >> 4, bn4 = t & 15;

    float acc[2][4][4];
    #pragma unroll
    for (int mt = 0; mt < 2; mt++)
        #pragma unroll
        for (int nt = 0; nt < 4; nt++)
            #pragma unroll
            for (int q = 0; q < 4; q++) acc[mt][nt][q] = 0.f;

    const int NT = K/16;

    // prologue: tile 0
    {
        #pragma unroll
        for (int u = 0; u < 2; u++) {
            int row = ar0 + u*64;
            int grow = row0 + row;
            float4 v = make_float4(0,0,0,0);
            if (grow < M) v = *(const float4*)(A + (size_t)grow*K + akq*4);
            float4 w = make_float4(totf(v.x), totf(v.y), totf(v.z), totf(v.w));
            *(float4*)&As[0][row][akq*4] = w;
        }
        float4 v = *(const float4*)(B + (size_t)bk*Nn + col0 + bn4*4);
        float4 w = make_float4(totf(v.x), totf(v.y), totf(v.z), totf(v.w));
        *(float4*)&Bs[0][bk][bn4*4] = w;
    }
    __syncthreads();

    for (int kt = 0; kt < NT; kt++) {
        const int buf = kt & 1;
        const bool more = (kt+1 < NT);
        float4 na[2], nb;
        if (more) {
            #pragma unroll
            for (int u = 0; u < 2; u++) {
                int row = ar0 + u*64;
                int grow = row0 + row;
                na[u] = make_float4(0,0,0,0);
                if (grow < M) na[u] = *(const float4*)(A + (size_t)grow*K + (kt+1)*16 + akq*4);
            }
            nb = *(const float4*)(B + (size_t)((kt+1)*16 + bk)*Nn + col0 + bn4*4);
        }

        #pragma unroll
        for (int ks = 0; ks < 2; ks++) {
            const int k0 = ks*8;
            uint32_t a[2][4], b[4][2];
            #pragma unroll
            for (int mt = 0; mt < 2; mt++) {
                const int arow = warp_m*32 + mt*16 + g;
                a[mt][0] = __float_as_uint(As[buf][arow    ][k0 + tg]);
                a[mt][1] = __float_as_uint(As[buf][arow + 8][k0 + tg]);
                a[mt][2] = __float_as_uint(As[buf][arow    ][k0 + tg + 4]);
                a[mt][3] = __float_as_uint(As[buf][arow + 8][k0 + tg + 4]);
            }
            #pragma unroll
            for (int nt = 0; nt < 4; nt++) {
                const int bcol = warp_n*32 + nt*8 + g;
                b[nt][0] = __float_as_uint(Bs[buf][k0 + tg    ][bcol]);
                b[nt][1] = __float_as_uint(Bs[buf][k0 + tg + 4][bcol]);
            }
            #pragma unroll
            for (int mt = 0; mt < 2; mt++)
                #pragma unroll
                for (int nt = 0; nt < 4; nt++)
                    asm volatile(
                        "mma.sync.aligned.m16n8k8.row.col.f32.tf32.tf32.f32 "
                        "{%0,%1,%2,%3}, {%4,%5,%6,%7}, {%8,%9}, {%0,%1,%2,%3};"
                        : "+f"(acc[mt][nt][0]), "+f"(acc[mt][nt][1]),
                          "+f"(acc[mt][nt][2]), "+f"(acc[mt][nt][3])
                        : "r"(a[mt][0]), "r"(a[mt][1]), "r"(a[mt][2]), "r"(a[mt][3]),
                          "r"(b[nt][0]), "r"(b[nt][1]));
        }

        if (more) {
            const int nbuf = buf ^ 1;
            #pragma unroll
            for (int u = 0; u < 2; u++) {
                int row = ar0 + u*64;
                float4 w = make_float4(totf(na[u].x), totf(na[u].y), totf(na[u].z), totf(na[u].w));
                *(float4*)&As[nbuf][row][akq*4] = w;
            }
            float4 w = make_float4(totf(nb.x), totf(nb.y), totf(nb.z), totf(nb.w));
            *(float4*)&Bs[nbuf][bk][bn4*4] = w;
        }
        __syncthreads();
    }

    // epilogue
    #pragma unroll
    for (int mt = 0; mt < 2; mt++) {
        #pragma unroll
        for (int nt = 0; nt < 4; nt++) {
            const int c = col0 + warp_n*32 + nt*8 + 2*tg;
            float bb0 = 0.f, bb1 = 0.f;
            if (BIAS) { bb0 = bias[c]; bb1 = bias[c+1]; }
            #pragma unroll
            for (int half = 0; half < 2; half++) {
                const int r = row0 + warp_m*32 + mt*16 + g + half*8;
                if (r >= M) continue;
                float o0 = acc[mt][nt][half*2+0] + bb0;
                float o1 = acc[mt][nt][half*2+1] + bb1;
                if (SILU) {
                    o0 = o0 / (1.0f + __expf(-o0));
                    o1 = o1 / (1.0f + __expf(-o1));
                }
                *(float2*)(C + (size_t)r*Nn + c) = make_float2(o0, o1);
            }
        }
    }
}

// ---------------- CSR edge kernel (no atomics) -------------------------------
__global__ void __launch_bounds__(128) k_edge(
        const float* __restrict__ dW,     // [20][384]
        const float* __restrict__ db,     // [384]
        const float* __restrict__ phi,    // [N][384]
        const float* __restrict__ s1,
        const float* __restrict__ v1,     // [3][N][128]
        float* __restrict__ s2,
        float* __restrict__ v2)
{
    const int i = blockIdx.x, f = threadIdx.x;
    __shared__ float s_rbf [32*NRBF_K];
    __shared__ float s_unit[32*3];
    __shared__ float s_fc  [32];
    __shared__ int   s_jj  [32];

    float wA[NRBF_K], wB[NRBF_K], wC[NRBF_K];
    #pragma unroll
    for (int k = 0; k < NRBF_K; k++) {
        wA[k] = dW[k*PHI_D + f];
        wB[k] = dW[k*PHI_D + 128 + f];
        wC[k] = dW[k*PHI_D + 256 + f];
    }
    const float bA = db[f], bB = db[128+f], bC = db[256+f];
    const int r0 = g_roff[i], r1 = g_roff[i+1];

    float accS = 0.f, aV0 = 0.f, aV1 = 0.f, aV2 = 0.f;
    for (int base = r0; base < r1; base += 32) {
        const int cnt = min(32, r1 - base);
        __syncthreads();
        for (int idx = f; idx < cnt*NRBF_K; idx += 128) s_rbf[idx]  = g_rbfs[base*NRBF_K + idx];
        for (int idx = f; idx < cnt*3;      idx += 128) s_unit[idx] = g_unit[base*3 + idx];
        if (f < cnt) { s_fc[f] = g_fc[base+f]; s_jj[f] = g_sj[base+f]; }
        __syncthreads();
        for (int t = 0; t < cnt; t++) {
            const float fcv = s_fc[t];
            float w0 = fcv*bA, w1 = fcv*bB, w2 = fcv*bC;
            #pragma unroll
            for (int k = 0; k < NRBF_K; k++) {
                const float r = s_rbf[t*NRBF_K + k];
                w0 = fmaf(r, wA[k], w0);
                w1 = fmaf(r, wB[k], w1);
                w2 = fmaf(r, wC[k], w2);
            }
            const int j = s_jj[t];
            const float* pj = phi + (size_t)j*PHI_D;
            const float i0 = pj[f]*w0, i1 = pj[128+f]*w1, i2 = pj[256+f]*w2;
            accS += i0;
            const float* vj = v1 + (size_t)j*FDIM + f;
            aV0 = fmaf(i1, vj[0],    fmaf(i2, s_unit[t*3+0], aV0));
            aV1 = fmaf(i1, vj[NF],   fmaf(i2, s_unit[t*3+1], aV1));
            aV2 = fmaf(i1, vj[2*NF], fmaf(i2, s_unit[t*3+2], aV2));
        }
    }
    const size_t o = (size_t)i*FDIM + f;
    s2[o]        = s1[o]        + accS;
    v2[o]        = v1[o]        + aV0;
    v2[o + NF]   = v1[o + NF]   + aV1;
    v2[o + 2*NF] = v1[o + 2*NF] + aV2;
}

// ---------------- update-phase elementwise kernels ---------------------------
__global__ void k_cat(const float* __restrict__ s2, const float* __restrict__ uvvv,
                      float* __restrict__ cat) {
    int idx = blockIdx.x*blockDim.x + threadIdx.x;
    if (idx >= NF) return;
    int n = idx >> 7, g = idx & 127;
    float w0 = uvvv[((size_t)(0*NA+n))*256 + 128 + g];
    float w1 = uvvv[((size_t)(1*NA+n))*256 + 128 + g];
    float w2 = uvvv[((size_t)(2*NA+n))*256 + 128 + g];
    cat[n*256 + g]       = s2[idx];
    cat[n*256 + 128 + g] = sqrtf(w0*w0 + w1*w1 + w2*w2 + EPS_F);
}

__global__ void k_combine(const float* __restrict__ s2, const float* __restrict__ v2,
                          const float* __restrict__ uvvv, const float* __restrict__ aw,
                          float* __restrict__ sOut, float* __restrict__ vOut) {
    int idx = blockIdx.x*blockDim.x + threadIdx.x;
    if (idx >= NF) return;
    int n = idx >> 7, f = idx & 127;
    float a0 = aw[(size_t)n*PHI_D + f];
    float a1 = aw[(size_t)n*PHI_D + 128 + f];
    float a2 = aw[(size_t)n*PHI_D + 256 + f];
    float u0 = uvvv[((size_t)(0*NA+n))*256 + f];
    float u1 = uvvv[((size_t)(1*NA+n))*256 + f];
    float u2 = uvvv[((size_t)(2*NA+n))*256 + f];
    float w0 = uvvv[((size_t)(0*NA+n))*256 + 128 + f];
    float w1 = uvvv[((size_t)(1*NA+n))*256 + 128 + f];
    float w2 = uvvv[((size_t)(2*NA+n))*256 + 128 + f];
    float dot = u0*w0 + u1*w1 + u2*w2;
    sOut[idx]        = s2[idx] + a1*dot + a2;
    vOut[idx]        = v2[idx]        + u0*a0;
    vOut[idx + NF]   = v2[idx + NF]   + u1*a0;
    vOut[idx + 2*NF] = v2[idx + 2*NF] + u2*a0;
}

// ---------------- readout ----------------------------------------------------
__global__ void k_readout(const float* __restrict__ hid, const float* __restrict__ W2,
                          const float* __restrict__ b2, const int* __restrict__ mol,
                          float* __restrict__ out) {
    int n = blockIdx.x*blockDim.x + threadIdx.x;
    if (n >= NA) return;
    float acc = b2[0];
    const float* h = hid + (size_t)n*64;
    #pragma unroll
    for (int k = 0; k < 64; k++) acc = fmaf(h[k], W2[k], acc);
    atomicAdd(&out[mol[n]], acc);
}

// ---------------- host-side orchestration ------------------------------------
extern "C" void kernel_launch(void* const* d_in, const int* in_sizes, int n_in,
                              void* d_out, int out_size) {
    const float* xyz    = (const float*)d_in[0];
    const int*   z      = (const int*)  d_in[1];
    const int*   nbrs   = (const int*)  d_in[2];
    const int*   mol    = (const int*)  d_in[3];
    const float* emb    = (const float*)d_in[4];
    const float* msgW1  = (const float*)d_in[5];
    const float* msgb1  = (const float*)d_in[6];
    const float* msgW2  = (const float*)d_in[7];
    const float* msgb2  = (const float*)d_in[8];
    const float* distW  = (const float*)d_in[9];
    const float* distb  = (const float*)d_in[10];
    const float* updU   = (const float*)d_in[11];
    const float* updV   = (const float*)d_in[12];
    const float* updW1  = (const float*)d_in[13];
    const float* updb1  = (const float*)d_in[14];
    const float* updW2  = (const float*)d_in[15];
    const float* updb2  = (const float*)d_in[16];
    const float* readW1 = (const float*)d_in[17];
    const float* readb1 = (const float*)d_in[18];
    const float* readW2 = (const float*)d_in[19];
    const float* readb2 = (const float*)d_in[20];
    float* out = (float*)d_out;

    float *s1, *s2, *v1, *v2, *phi, *hid, *cat, *uvvv, *aw, *Bcat;
    cudaGetSymbolAddress((void**)&s1,   g_s1);
    cudaGetSymbolAddress((void**)&s2,   g_s2);
    cudaGetSymbolAddress((void**)&v1,   g_v1);
    cudaGetSymbolAddress((void**)&v2,   g_v2);
    cudaGetSymbolAddress((void**)&phi,  g_phi);
    cudaGetSymbolAddress((void**)&hid,  g_hid);
    cudaGetSymbolAddress((void**)&cat,  g_cat);
    cudaGetSymbolAddress((void**)&uvvv, g_uvvv);
    cudaGetSymbolAddress((void**)&aw,   g_aw);
    cudaGetSymbolAddress((void**)&Bcat, g_Bcat);

    const int TPB = 256;
    // prep: 5 launches, so launch #6 (first tf32 GEMM) is the ncu target
    k_catUV<<<(NLAYERS*FDIM*256 + TPB-1)/TPB, TPB>>>(updU, updV);  // 1 (also zeros g_cnt)
    k_count<<<NE/TPB, TPB>>>(nbrs);                                // 2
    k_scan <<<1, 1024>>>();                                        // 3 (also inits g_cur)
    k_fill <<<NE/TPB, TPB>>>(nbrs);                                // 4
    k_prepgeom<<<NF/TPB, TPB>>>(xyz, nbrs, z, emb);                // 5

    const int GY1 = (NA + 127)/128;       // 79
    const int GY3 = (3*NA + 127)/128;     // 235
    for (int l = 0; l < NLAYERS; l++) {
        const float* mW1 = msgW1 + (size_t)l*128*128;
        const float* mb1 = msgb1 + (size_t)l*128;
        const float* mW2 = msgW2 + (size_t)l*128*384;
        const float* mb2 = msgb2 + (size_t)l*384;
        const float* dW  = distW + (size_t)l*NRBF_K*384;
        const float* dbv = distb + (size_t)l*384;
        const float* uW1 = updW1 + (size_t)l*256*128;
        const float* ub1 = updb1 + (size_t)l*128;
        const float* uW2 = updW2 + (size_t)l*128*384;
        const float* ub2 = updb2 + (size_t)l*384;
        const float* Bc  = Bcat  + (size_t)l*128*256;

        // phi = silu(s@W1 + b1)@W2 + b2
        k_tgemm<true,  true><<<dim3(2, GY1), 256>>>(s1,  mW1, mb1, hid, NA, 128, 128);   // launch 6 (profiled)
        k_tgemm<false, true><<<dim3(6, GY1), 256>>>(hid, mW2, mb2, phi, NA, 384, 128);
        // edge aggregation (CSR, no atomics): s2 = s1 + ds, v2 = v1 + dv
        k_edge<<<NA, 128>>>(dW, dbv, phi, s1, v1, s2, v2);
        // update phase: [uv | vv] in one GEMM (N=256)
        k_tgemm<false, false><<<dim3(4, GY3), 256>>>(v2, Bc, (const float*)nullptr, uvvv, 3*NA, 256, 128);
        k_cat<<<NF/TPB, TPB>>>(s2, uvvv, cat);
        k_tgemm<true,  true><<<dim3(2, GY1), 256>>>(cat, uW1, ub1, hid, NA, 128, 256);
        k_tgemm<false, true><<<dim3(6, GY1), 256>>>(hid, uW2, ub2, aw,  NA, 384, 128);
        k_combine<<<NF/TPB, TPB>>>(s2, v2, uvvv, aw, s1, v1);
    }

    // readout
    k_tgemm<true, true><<<dim3(1, GY1), 256>>>(s1, readW1, readb1, hid, NA, 64, 128);
    cudaMemsetAsync(out, 0, NMOLS*sizeof(float));
    k_readout<<<(NA + TPB-1)/TPB, TPB>>>(hid, readW2, readb2, mol, out);
}